// round 9
// baseline (speedup 1.0000x reference)
#include <cuda_runtime.h>
#include <math.h>

#define NB 64
#define V 256
#define F 64
#define C 64
#define ALPHA_C 0.1f
#define YSZ (NB * V * F)

typedef unsigned long long ull;

// ---------------- packed f32x2 helpers (FFMA2 path, PTX-only) ----------------
__device__ __forceinline__ ull pk2(float v) {
    ull r;
    asm("mov.b64 %0, {%1, %1};" : "=l"(r) : "f"(v));
    return r;
}
__device__ __forceinline__ ull add2(ull a, ull b) {
    ull r;
    asm("add.rn.f32x2 %0, %1, %2;" : "=l"(r) : "l"(a), "l"(b));
    return r;
}
__device__ __forceinline__ ull mul2(ull a, ull b) {
    ull r;
    asm("mul.rn.f32x2 %0, %1, %2;" : "=l"(r) : "l"(a), "l"(b));
    return r;
}
__device__ __forceinline__ ull fma2(ull a, ull b, ull c) {
    ull r;
    asm("fma.rn.f32x2 %0, %1, %2, %3;" : "=l"(r) : "l"(a), "l"(b), "l"(c));
    return r;
}
__device__ __forceinline__ void upk2(ull v, float& lo, float& hi) {
    asm("mov.b64 {%0, %1}, %2;" : "=f"(lo), "=f"(hi) : "l"(v));
}
#define ABS2_MASK 0x7FFFFFFF7FFFFFFFULL

// ---------------- scratch (no allocations allowed) ----------------
__device__ float g_pc[NB * 4 * V];   // colsum partials, 4 slots per column block
__device__ float g_pA[NB * 4 * V];   // sum tmp^2 partials
__device__ float g_pB[NB * 4 * V];   // sum tmp*d2 partials
__device__ float g_lossP[NB * 4];    // per (b, ks) loss partials
__device__ float g_Y[3 * YSZ];       // Y0 = x@(th0-th2), Y1 = x@(-th1), Y2 = x@(2*th2)
__device__ float g_part[4 * YSZ];    // k-split partial sums of s@Y1 + (s*s)@Y2
__device__ int g_cnt[NB * 2];        // per (b, it) arrival counters (zero-init; reset after use)
__device__ int g_cntG;               // global arrival counter

// upper-triangle 4x4 tile enumeration (10 tiles)
__constant__ int c_IT[10] = {0, 0, 0, 0, 1, 1, 1, 2, 2, 3};
__constant__ int c_JT[10] = {0, 1, 2, 3, 1, 2, 3, 2, 3, 3};

#define N_PW 640   // pairwise blocks: 10 tiles x 64 b
#define N_YG 768   // y-gemm blocks: 4 it x 3 m x 64 b

#define POOL_F 10880

// partial-array offsets (overlay xj region, each 64*17=1088 floats)
#define P_CC 4352
#define P_AC (4352 + 1088)
#define P_BC (4352 + 2176)
#define P_CR (4352 + 3264)
#define P_AR (4352 + 4352)
#define P_BR (4352 + 5440)

// ---------------- mega kernel 1: pairwise (idx<640) + y_gemm (idx>=640) ----------------
__global__ __launch_bounds__(256) void mega1_kernel(
    const float* __restrict__ x, const float* __restrict__ a,
    const float* __restrict__ theta, float* __restrict__ s_out) {
    __shared__ __align__(16) float pool[POOL_F];

    const int t = threadIdx.x;
    const int tx = t & 15, ty = t >> 4;

    if (blockIdx.x >= N_PW) {
        // ================= y_gemm part =================
        int idx = blockIdx.x - N_PW;
        const int it = idx & 3;
        const int m = (idx >> 2) % 3;
        const int b = idx / 12;
        const int i0 = it * 64;
        float (*sW)[64] = (float(*)[64])pool;          // 4096
        float (*sX)[68] = (float(*)[68])(pool + 4096); // 4352
        const float* xb = x + b * V * F;

        for (int q = t; q < 64 * 16; q += 256) {
            int f = q >> 4;
            int c4 = (q & 15) * 4;
            float4 v;
            if (m == 0) {
                float4 t0 = *(const float4*)&theta[(0 * F + f) * C + c4];
                float4 t2 = *(const float4*)&theta[(2 * F + f) * C + c4];
                v = make_float4(t0.x - t2.x, t0.y - t2.y, t0.z - t2.z, t0.w - t2.w);
            } else if (m == 1) {
                float4 t1 = *(const float4*)&theta[(1 * F + f) * C + c4];
                v = make_float4(-t1.x, -t1.y, -t1.z, -t1.w);
            } else {
                float4 t2 = *(const float4*)&theta[(2 * F + f) * C + c4];
                v = make_float4(2.f * t2.x, 2.f * t2.y, 2.f * t2.z, 2.f * t2.w);
            }
            *(float4*)&sW[f][c4] = v;
        }
        for (int q = t; q < 64 * 16; q += 256) {
            int i = q >> 4;
            int f4 = (q & 15) * 4;
            float4 v = *(const float4*)&xb[(i0 + i) * F + f4];
            sX[f4 + 0][i] = v.x;
            sX[f4 + 1][i] = v.y;
            sX[f4 + 2][i] = v.z;
            sX[f4 + 3][i] = v.w;
        }
        __syncthreads();

        ull acc2[4][2];
#pragma unroll
        for (int ii = 0; ii < 4; ii++)
#pragma unroll
            for (int p = 0; p < 2; p++) acc2[ii][p] = 0ULL;

#pragma unroll 4
        for (int k = 0; k < 64; k++) {
            float4 xa = *(const float4*)&sX[k][ty * 4];
            ulonglong2 wp = *(const ulonglong2*)&sW[k][tx * 4];
            float xv[4] = {xa.x, xa.y, xa.z, xa.w};
#pragma unroll
            for (int ii = 0; ii < 4; ii++) {
                ull xv2 = pk2(xv[ii]);
                acc2[ii][0] = fma2(xv2, wp.x, acc2[ii][0]);
                acc2[ii][1] = fma2(xv2, wp.y, acc2[ii][1]);
            }
        }

        float* y = g_Y + m * YSZ + b * V * F;
#pragma unroll
        for (int ii = 0; ii < 4; ii++) {
            int row = i0 + ty * 4 + ii;
            float4 o;
            upk2(acc2[ii][0], o.x, o.y);
            upk2(acc2[ii][1], o.z, o.w);
            *(float4*)&y[row * F + tx * 4] = o;
        }
        return;
    }

    // ================= pairwise part =================
    const int b = blockIdx.x / 10;
    const int tile = blockIdx.x % 10;
    const int it = c_IT[tile], jt = c_JT[tile];
    const int i0 = it * 64, j0 = jt * 64;
    const bool offdiag = (it != jt);
    const float* xb = x + b * V * F;

    float (*xi_t)[68] = (float(*)[68])pool;           // 4352
    float (*xj_t)[68] = (float(*)[68])(pool + 4352);  // 4352, stores NEGATED xj
    float* a_s = pool + 8704;                         // 64 (dead after main loop)

    for (int e = t; e < 64 * F; e += 256) {
        int row = e >> 6;
        int f = e & 63;
        xi_t[f][row] = xb[(i0 + row) * F + f];
        xj_t[f][row] = -xb[(j0 + row) * F + f];  // negated: d = xi + (-xj)
    }
    if (t < F) a_s[t] = a[t];
    __syncthreads();

    ull sc2[4][2], dd2[4][2];
#pragma unroll
    for (int ii = 0; ii < 4; ii++)
#pragma unroll
        for (int p = 0; p < 2; p++) { sc2[ii][p] = 0ULL; dd2[ii][p] = 0ULL; }

#pragma unroll 4
    for (int f = 0; f < F; f++) {
        float4 xi4 = *(const float4*)&xi_t[f][ty * 4];
        ulonglong2 xjp = *(const ulonglong2*)&xj_t[f][tx * 4];
        float xiv[4] = {xi4.x, xi4.y, xi4.z, xi4.w};
        ull af2 = pk2(a_s[f]);
#pragma unroll
        for (int ii = 0; ii < 4; ii++) {
            ull xi2 = pk2(xiv[ii]);
            ull d0 = add2(xi2, xjp.x);
            ull d1 = add2(xi2, xjp.y);
            sc2[ii][0] = fma2(d0 & ABS2_MASK, af2, sc2[ii][0]);
            sc2[ii][1] = fma2(d1 & ABS2_MASK, af2, sc2[ii][1]);
            dd2[ii][0] = fma2(d0, d0, dd2[ii][0]);
            dd2[ii][1] = fma2(d1, d1, dd2[ii][1]);
        }
    }

    // unpack to scalars
    float sc[4][4], dd[4][4];
#pragma unroll
    for (int ii = 0; ii < 4; ii++)
#pragma unroll
        for (int p = 0; p < 2; p++) {
            upk2(sc2[ii][p], sc[ii][2 * p], sc[ii][2 * p + 1]);
            upk2(dd2[ii][p], dd[ii][2 * p], dd[ii][2 * p + 1]);
        }

    float tm[4][4];
    float cpart[4] = {0.f, 0.f, 0.f, 0.f};
    float Apart[4] = {0.f, 0.f, 0.f, 0.f};
    float Bpart[4] = {0.f, 0.f, 0.f, 0.f};
    float rc[4] = {0.f, 0.f, 0.f, 0.f};
    float rA[4] = {0.f, 0.f, 0.f, 0.f};
    float rB[4] = {0.f, 0.f, 0.f, 0.f};

#pragma unroll
    for (int ii = 0; ii < 4; ii++) {
#pragma unroll
        for (int jj = 0; jj < 4; jj++) {
            float tmp = __expf(-fmaxf(sc[ii][jj], 0.f));
            tm[ii][jj] = tmp;
            float t2 = tmp * tmp;
            float td = tmp * dd[ii][jj];
            cpart[jj] += tmp; Apart[jj] += t2; Bpart[jj] += td;
            rc[ii] += tmp;    rA[ii] += t2;    rB[ii] += td;
        }
    }

    __syncthreads();  // xi/xj/a_s reads complete; safe to overlay

    float* sb = s_out + (size_t)b * V * V;
#pragma unroll
    for (int ii = 0; ii < 4; ii++) {
        *(float4*)&sb[(i0 + ty * 4 + ii) * V + j0 + tx * 4] =
            make_float4(tm[ii][0], tm[ii][1], tm[ii][2], tm[ii][3]);
    }

    // non-atomic partial stores: [col][ty] / [row][tx], pad 17 (all scalar)
#pragma unroll
    for (int jj = 0; jj < 4; jj++) {
        int col = tx * 4 + jj;
        pool[P_CC + col * 17 + ty] = cpart[jj];
        pool[P_AC + col * 17 + ty] = Apart[jj];
        pool[P_BC + col * 17 + ty] = Bpart[jj];
    }
    if (offdiag) {
#pragma unroll
        for (int ii = 0; ii < 4; ii++) {
            int row = ty * 4 + ii;
            pool[P_CR + row * 17 + tx] = rc[ii];
            pool[P_AR + row * 17 + tx] = rA[ii];
            pool[P_BR + row * 17 + tx] = rB[ii];
        }
        // transpose tm into xi region for the mirror write
#pragma unroll
        for (int jj = 0; jj < 4; jj++) {
            *(float4*)&xi_t[tx * 4 + jj][ty * 4] =
                make_float4(tm[0][jj], tm[1][jj], tm[2][jj], tm[3][jj]);
        }
    }
    __syncthreads();

    if (t < 64) {
        float cs = 0.f, As = 0.f, Bs = 0.f;
#pragma unroll
        for (int u = 0; u < 16; u++) {
            cs += pool[P_CC + t * 17 + u];
            As += pool[P_AC + t * 17 + u];
            Bs += pool[P_BC + t * 17 + u];
        }
        int bc = (b * 4 + it) * V + j0 + t;
        g_pc[bc] = cs; g_pA[bc] = As; g_pB[bc] = Bs;
        if (offdiag) {
            float cr = 0.f, Ar = 0.f, Br = 0.f;
#pragma unroll
            for (int u = 0; u < 16; u++) {
                cr += pool[P_CR + t * 17 + u];
                Ar += pool[P_AR + t * 17 + u];
                Br += pool[P_BR + t * 17 + u];
            }
            int br = (b * 4 + jt) * V + i0 + t;
            g_pc[br] = cr; g_pA[br] = Ar; g_pB[br] = Br;
        }
    }

    if (offdiag) {
        for (int e = t; e < 64 * 16; e += 256) {
            int row = e >> 4;
            int c4 = (e & 15) * 4;
            *(float4*)&sb[(j0 + row) * V + i0 + c4] = *(float4*)&xi_t[row][c4];
        }
    }
}

// ---------------- stage 2: k-split GEMM + normalization + loss + FINISHER epilogue ----------------
// Grid: (8 = 2 i-tiles x 4 k-splits, 64 b); 256 threads; block tile 128x64, K=64/block.
// Last-arriving block per (b,it) assembles gcn = relu(Y0 + sum partials); globally
// last block writes the loss scalar. Counters self-reset for graph replay.
__global__ __launch_bounds__(256) void fused_gemm_kernel(
    float* __restrict__ s_out, float* __restrict__ gcn, float* __restrict__ out_loss) {
    __shared__ __align__(16) float sA[128][36];  // [i][k] normalized s chunk
    __shared__ __align__(16) float sY1[32][64];  // Y1 chunk [k][c]
    __shared__ __align__(16) float sY2[32][64];  // Y2 chunk [k][c]
    __shared__ __align__(16) float sR[64];       // 1/colsum for this block's 64 k-cols
    __shared__ int s_last, s_lastG;

    const int b = blockIdx.y;
    const int it = blockIdx.x & 1, ks = blockIdx.x >> 1;
    const int i0 = it * 128;
    const int t = threadIdx.x;
    const int tx = t & 15, ty = t >> 4;

    if (t < 64) {
        int base = b * 4 * V + ks * 64 + t;
        float cs = g_pc[base] + g_pc[base + V] + g_pc[base + 2 * V] + g_pc[base + 3 * V];
        sR[t] = 1.0f / cs;
    }
    if (it == 0) {
        float* red = (float*)sY1;  // scratch before staging
        if (t < 64) {
            int base = b * 4 * V + ks * 64 + t;
            float cs = g_pc[base] + g_pc[base + V] + g_pc[base + 2 * V] + g_pc[base + 3 * V];
            float A = g_pA[base] + g_pA[base + V] + g_pA[base + 2 * V] + g_pA[base + 3 * V];
            float B = g_pB[base] + g_pB[base + V] + g_pB[base + 2 * V] + g_pB[base + 3 * V];
            float r = 1.0f / cs;
            red[t] = A * r * r + ALPHA_C * B * r;
        }
        __syncthreads();
        for (int s = 32; s > 0; s >>= 1) {
            if (t < s) red[t] += red[t + s];
            __syncthreads();
        }
        if (t == 0) g_lossP[b * 4 + ks] = red[0];
    }
    __syncthreads();

    float* sb = s_out + (size_t)b * V * V;
    const float* y1 = g_Y + 1 * YSZ + b * V * F;
    const float* y2 = g_Y + 2 * YSZ + b * V * F;

    ull acc2[8][2];
#pragma unroll
    for (int ii = 0; ii < 8; ii++) { acc2[ii][0] = 0ULL; acc2[ii][1] = 0ULL; }

    for (int chunk = 0; chunk < 2; chunk++) {
        int k0 = ks * 64 + chunk * 32;
        int cl = chunk * 32;
        for (int q = t; q < 128 * 8; q += 256) {
            int i = q >> 3;
            int k4 = (q & 7) * 4;
            float* addr = &sb[(i0 + i) * V + k0 + k4];
            float4 v = *(const float4*)addr;
            float4 rv = *(const float4*)&sR[cl + k4];
            v.x *= rv.x; v.y *= rv.y; v.z *= rv.z; v.w *= rv.w;
            *(float4*)addr = v;  // write back normalized s (disjoint cols per ks)
            *(float4*)&sA[i][k4] = v;
        }
        for (int q = t; q < 32 * 16; q += 256) {
            int k = q >> 4;
            int f4 = (q & 15) * 4;
            *(float4*)&sY1[k][f4] = *(const float4*)&y1[(k0 + k) * F + f4];
            *(float4*)&sY2[k][f4] = *(const float4*)&y2[(k0 + k) * F + f4];
        }
        __syncthreads();

#pragma unroll
        for (int kk = 0; kk < 8; kk++) {
            float a_[8][4];
#pragma unroll
            for (int ii = 0; ii < 8; ii++)
                *(float4*)a_[ii] = *(const float4*)&sA[ty * 8 + ii][kk * 4];
#pragma unroll
            for (int kq = 0; kq < 4; kq++) {
                int k = kk * 4 + kq;
                ulonglong2 b1p = *(const ulonglong2*)&sY1[k][tx * 4];
                ulonglong2 b2p = *(const ulonglong2*)&sY2[k][tx * 4];
#pragma unroll
                for (int ii = 0; ii < 8; ii++) {
                    ull av2 = pk2(a_[ii][kq]);
                    ull a22 = mul2(av2, av2);
                    acc2[ii][0] = fma2(av2, b1p.x, acc2[ii][0]);
                    acc2[ii][1] = fma2(av2, b1p.y, acc2[ii][1]);
                    acc2[ii][0] = fma2(a22, b2p.x, acc2[ii][0]);
                    acc2[ii][1] = fma2(a22, b2p.y, acc2[ii][1]);
                }
            }
        }
        __syncthreads();
    }

    float* p = g_part + ks * YSZ + b * V * F;
#pragma unroll
    for (int ii = 0; ii < 8; ii++) {
        int row = i0 + ty * 8 + ii;
        float4 o;
        upk2(acc2[ii][0], o.x, o.y);
        upk2(acc2[ii][1], o.z, o.w);
        *(float4*)&p[row * F + tx * 4] = o;
    }

    // -------- finisher protocol (threadfence reduction pattern) --------
    __threadfence();
    __syncthreads();
    if (t == 0) {
        int o = atomicAdd(&g_cnt[b * 2 + it], 1);
        s_last = (o == 3) ? 1 : 0;
        int og = atomicAdd(&g_cntG, 1);
        s_lastG = (og == NB * 8 - 1) ? 1 : 0;
    }
    __syncthreads();

    if (s_last) {
        if (t == 0) g_cnt[b * 2 + it] = 0;  // reset for next replay
        __threadfence();
        const float* y0b = g_Y + b * V * F + i0 * F;          // rows i0..i0+127
        const float* p0 = g_part + 0 * YSZ + b * V * F + i0 * F;
        const float* p1 = g_part + 1 * YSZ + b * V * F + i0 * F;
        const float* p2 = g_part + 2 * YSZ + b * V * F + i0 * F;
        const float* p3 = g_part + 3 * YSZ + b * V * F + i0 * F;
        float* g = gcn + b * V * C + i0 * C;
        for (int q = t; q < 128 * 16; q += 256) {  // 2048 float4
            float4 y = ((const float4*)y0b)[q];
            float4 a0 = ((const float4*)p0)[q];
            float4 a1 = ((const float4*)p1)[q];
            float4 a2 = ((const float4*)p2)[q];
            float4 a3 = ((const float4*)p3)[q];
            float4 o = make_float4(fmaxf(y.x + a0.x + a1.x + a2.x + a3.x, 0.f),
                                   fmaxf(y.y + a0.y + a1.y + a2.y + a3.y, 0.f),
                                   fmaxf(y.z + a0.z + a1.z + a2.z + a3.z, 0.f),
                                   fmaxf(y.w + a0.w + a1.w + a2.w + a3.w, 0.f));
            ((float4*)g)[q] = o;
        }
    }

    if (s_lastG && t == 0) {
        g_cntG = 0;  // reset for next replay
        __threadfence();
        float acc = 0.f;
#pragma unroll 8
        for (int i = 0; i < NB * 4; i++) acc += g_lossP[i];
        *out_loss = acc;
    }
}

// ---------------- launch ----------------
extern "C" void kernel_launch(void* const* d_in, const int* in_sizes, int n_in,
                              void* d_out, int out_size) {
    const float* x = (const float*)d_in[0];      // (64,256,64)
    const float* a = (const float*)d_in[1];      // (64,)
    const float* theta = (const float*)d_in[2];  // (3,64,64)

    float* out = (float*)d_out;
    float* gcn = out;                                 // NB*V*C
    float* s_out = out + (size_t)NB * V * C;          // NB*V*V
    float* loss = out + (size_t)NB * V * C + (size_t)NB * V * V;  // 1

    mega1_kernel<<<N_PW + N_YG, 256>>>(x, a, theta, s_out);

    dim3 gB(8, NB);
    fused_gemm_kernel<<<gB, 256>>>(s_out, gcn, loss);
}

// round 10
// speedup vs baseline: 1.4005x; 1.4005x over previous
#include <cuda_runtime.h>
#include <math.h>

#define NB 64
#define V 256
#define F 64
#define C 64
#define ALPHA_C 0.1f
#define YSZ (NB * V * F)

typedef unsigned long long ull;

// ---------------- packed f32x2 helpers (mega1 y-path) ----------------
__device__ __forceinline__ ull pk2(float v) {
    ull r;
    asm("mov.b64 %0, {%1, %1};" : "=l"(r) : "f"(v));
    return r;
}
__device__ __forceinline__ ull add2(ull a, ull b) {
    ull r;
    asm("add.rn.f32x2 %0, %1, %2;" : "=l"(r) : "l"(a), "l"(b));
    return r;
}
__device__ __forceinline__ ull fma2(ull a, ull b, ull c) {
    ull r;
    asm("fma.rn.f32x2 %0, %1, %2, %3;" : "=l"(r) : "l"(a), "l"(b), "l"(c));
    return r;
}
__device__ __forceinline__ void upk2(ull v, float& lo, float& hi) {
    asm("mov.b64 {%0, %1}, %2;" : "=f"(lo), "=f"(hi) : "l"(v));
}
#define ABS2_MASK 0x7FFFFFFF7FFFFFFFULL

// ---------------- tf32 mma helpers ----------------
__device__ __forceinline__ unsigned cvt_tf32(float f) {
    unsigned r;
    asm("cvt.rna.tf32.f32 %0, %1;" : "=r"(r) : "f"(f));
    return r;
}
__device__ __forceinline__ void mma_tf32(float* c,
    unsigned a0, unsigned a1, unsigned a2, unsigned a3,
    unsigned b0, unsigned b1) {
    asm("mma.sync.aligned.m16n8k8.row.col.f32.tf32.tf32.f32 "
        "{%0,%1,%2,%3}, {%4,%5,%6,%7}, {%8,%9}, {%0,%1,%2,%3};"
        : "+f"(c[0]), "+f"(c[1]), "+f"(c[2]), "+f"(c[3])
        : "r"(a0), "r"(a1), "r"(a2), "r"(a3), "r"(b0), "r"(b1));
}

// ---------------- scratch (no allocations allowed) ----------------
__device__ float g_pc[NB * 4 * V];
__device__ float g_pA[NB * 4 * V];
__device__ float g_pB[NB * 4 * V];
__device__ float g_lossP[NB];
__device__ float g_Y[3 * YSZ];   // Y0 = x@(th0-th2), Y1 = x@(-th1), Y2 = x@(2*th2)
__device__ int g_cntG;           // global arrival counter (zero-init; self-resetting)

__constant__ int c_IT[10] = {0, 0, 0, 0, 1, 1, 1, 2, 2, 3};
__constant__ int c_JT[10] = {0, 1, 2, 3, 1, 2, 3, 2, 3, 3};

#define N_PW 640
#define N_YG 768
#define POOL_F 10880
#define P_CC 4352
#define P_AC (4352 + 1088)
#define P_BC (4352 + 2176)
#define P_CR (4352 + 3264)
#define P_AR (4352 + 4352)
#define P_BR (4352 + 5440)

// ---------------- mega kernel 1: pairwise (idx<640) + y_gemm (idx>=640) ----------------
__global__ __launch_bounds__(256) void mega1_kernel(
    const float* __restrict__ x, const float* __restrict__ a,
    const float* __restrict__ theta, float* __restrict__ s_out) {
    __shared__ __align__(16) float pool[POOL_F];

    const int t = threadIdx.x;
    const int tx = t & 15, ty = t >> 4;

    if (blockIdx.x >= N_PW) {
        // ================= y_gemm part =================
        int idx = blockIdx.x - N_PW;
        const int it = idx & 3;
        const int m = (idx >> 2) % 3;
        const int b = idx / 12;
        const int i0 = it * 64;
        float (*sW)[64] = (float(*)[64])pool;
        float (*sX)[68] = (float(*)[68])(pool + 4096);
        const float* xb = x + b * V * F;

        for (int q = t; q < 64 * 16; q += 256) {
            int f = q >> 4;
            int c4 = (q & 15) * 4;
            float4 v;
            if (m == 0) {
                float4 t0 = *(const float4*)&theta[(0 * F + f) * C + c4];
                float4 t2 = *(const float4*)&theta[(2 * F + f) * C + c4];
                v = make_float4(t0.x - t2.x, t0.y - t2.y, t0.z - t2.z, t0.w - t2.w);
            } else if (m == 1) {
                float4 t1 = *(const float4*)&theta[(1 * F + f) * C + c4];
                v = make_float4(-t1.x, -t1.y, -t1.z, -t1.w);
            } else {
                float4 t2 = *(const float4*)&theta[(2 * F + f) * C + c4];
                v = make_float4(2.f * t2.x, 2.f * t2.y, 2.f * t2.z, 2.f * t2.w);
            }
            *(float4*)&sW[f][c4] = v;
        }
        for (int q = t; q < 64 * 16; q += 256) {
            int i = q >> 4;
            int f4 = (q & 15) * 4;
            float4 v = *(const float4*)&xb[(i0 + i) * F + f4];
            sX[f4 + 0][i] = v.x;
            sX[f4 + 1][i] = v.y;
            sX[f4 + 2][i] = v.z;
            sX[f4 + 3][i] = v.w;
        }
        __syncthreads();

        ull acc2[4][2];
#pragma unroll
        for (int ii = 0; ii < 4; ii++)
#pragma unroll
            for (int p = 0; p < 2; p++) acc2[ii][p] = 0ULL;

#pragma unroll 4
        for (int k = 0; k < 64; k++) {
            float4 xa = *(const float4*)&sX[k][ty * 4];
            ulonglong2 wp = *(const ulonglong2*)&sW[k][tx * 4];
            float xv[4] = {xa.x, xa.y, xa.z, xa.w};
#pragma unroll
            for (int ii = 0; ii < 4; ii++) {
                ull xv2 = pk2(xv[ii]);
                acc2[ii][0] = fma2(xv2, wp.x, acc2[ii][0]);
                acc2[ii][1] = fma2(xv2, wp.y, acc2[ii][1]);
            }
        }

        float* y = g_Y + m * YSZ + b * V * F;
#pragma unroll
        for (int ii = 0; ii < 4; ii++) {
            int row = i0 + ty * 4 + ii;
            float4 o;
            upk2(acc2[ii][0], o.x, o.y);
            upk2(acc2[ii][1], o.z, o.w);
            *(float4*)&y[row * F + tx * 4] = o;
        }
        return;
    }

    // ================= pairwise part =================
    const int b = blockIdx.x / 10;
    const int tile = blockIdx.x % 10;
    const int it = c_IT[tile], jt = c_JT[tile];
    const int i0 = it * 64, j0 = jt * 64;
    const bool offdiag = (it != jt);
    const float* xb = x + b * V * F;

    float (*xi_t)[68] = (float(*)[68])pool;
    float (*xj_t)[68] = (float(*)[68])(pool + 4352);
    float* a_s = pool + 8704;

    for (int e = t; e < 64 * F; e += 256) {
        int row = e >> 6;
        int f = e & 63;
        xi_t[f][row] = xb[(i0 + row) * F + f];
        xj_t[f][row] = -xb[(j0 + row) * F + f];
    }
    if (t < F) a_s[t] = a[t];
    __syncthreads();

    ull sc2[4][2], dd2[4][2];
#pragma unroll
    for (int ii = 0; ii < 4; ii++)
#pragma unroll
        for (int p = 0; p < 2; p++) { sc2[ii][p] = 0ULL; dd2[ii][p] = 0ULL; }

#pragma unroll 4
    for (int f = 0; f < F; f++) {
        float4 xi4 = *(const float4*)&xi_t[f][ty * 4];
        ulonglong2 xjp = *(const ulonglong2*)&xj_t[f][tx * 4];
        float xiv[4] = {xi4.x, xi4.y, xi4.z, xi4.w};
        ull af2 = pk2(a_s[f]);
#pragma unroll
        for (int ii = 0; ii < 4; ii++) {
            ull xi2 = pk2(xiv[ii]);
            ull d0 = add2(xi2, xjp.x);
            ull d1 = add2(xi2, xjp.y);
            sc2[ii][0] = fma2(d0 & ABS2_MASK, af2, sc2[ii][0]);
            sc2[ii][1] = fma2(d1 & ABS2_MASK, af2, sc2[ii][1]);
            dd2[ii][0] = fma2(d0, d0, dd2[ii][0]);
            dd2[ii][1] = fma2(d1, d1, dd2[ii][1]);
        }
    }

    float sc[4][4], dd[4][4];
#pragma unroll
    for (int ii = 0; ii < 4; ii++)
#pragma unroll
        for (int p = 0; p < 2; p++) {
            upk2(sc2[ii][p], sc[ii][2 * p], sc[ii][2 * p + 1]);
            upk2(dd2[ii][p], dd[ii][2 * p], dd[ii][2 * p + 1]);
        }

    float tm[4][4];
    float cpart[4] = {0.f, 0.f, 0.f, 0.f};
    float Apart[4] = {0.f, 0.f, 0.f, 0.f};
    float Bpart[4] = {0.f, 0.f, 0.f, 0.f};
    float rc[4] = {0.f, 0.f, 0.f, 0.f};
    float rA[4] = {0.f, 0.f, 0.f, 0.f};
    float rB[4] = {0.f, 0.f, 0.f, 0.f};

#pragma unroll
    for (int ii = 0; ii < 4; ii++) {
#pragma unroll
        for (int jj = 0; jj < 4; jj++) {
            float tmp = __expf(-fmaxf(sc[ii][jj], 0.f));
            tm[ii][jj] = tmp;
            float t2 = tmp * tmp;
            float td = tmp * dd[ii][jj];
            cpart[jj] += tmp; Apart[jj] += t2; Bpart[jj] += td;
            rc[ii] += tmp;    rA[ii] += t2;    rB[ii] += td;
        }
    }

    __syncthreads();

    float* sb = s_out + (size_t)b * V * V;
#pragma unroll
    for (int ii = 0; ii < 4; ii++) {
        *(float4*)&sb[(i0 + ty * 4 + ii) * V + j0 + tx * 4] =
            make_float4(tm[ii][0], tm[ii][1], tm[ii][2], tm[ii][3]);
    }

#pragma unroll
    for (int jj = 0; jj < 4; jj++) {
        int col = tx * 4 + jj;
        pool[P_CC + col * 17 + ty] = cpart[jj];
        pool[P_AC + col * 17 + ty] = Apart[jj];
        pool[P_BC + col * 17 + ty] = Bpart[jj];
    }
    if (offdiag) {
#pragma unroll
        for (int ii = 0; ii < 4; ii++) {
            int row = ty * 4 + ii;
            pool[P_CR + row * 17 + tx] = rc[ii];
            pool[P_AR + row * 17 + tx] = rA[ii];
            pool[P_BR + row * 17 + tx] = rB[ii];
        }
#pragma unroll
        for (int jj = 0; jj < 4; jj++) {
            *(float4*)&xi_t[tx * 4 + jj][ty * 4] =
                make_float4(tm[0][jj], tm[1][jj], tm[2][jj], tm[3][jj]);
        }
    }
    __syncthreads();

    if (t < 64) {
        float cs = 0.f, As = 0.f, Bs = 0.f;
#pragma unroll
        for (int u = 0; u < 16; u++) {
            cs += pool[P_CC + t * 17 + u];
            As += pool[P_AC + t * 17 + u];
            Bs += pool[P_BC + t * 17 + u];
        }
        int bc = (b * 4 + it) * V + j0 + t;
        g_pc[bc] = cs; g_pA[bc] = As; g_pB[bc] = Bs;
        if (offdiag) {
            float cr = 0.f, Ar = 0.f, Br = 0.f;
#pragma unroll
            for (int u = 0; u < 16; u++) {
                cr += pool[P_CR + t * 17 + u];
                Ar += pool[P_AR + t * 17 + u];
                Br += pool[P_BR + t * 17 + u];
            }
            int br = (b * 4 + jt) * V + i0 + t;
            g_pc[br] = cr; g_pA[br] = Ar; g_pB[br] = Br;
        }
    }

    if (offdiag) {
        for (int e = t; e < 64 * 16; e += 256) {
            int row = e >> 4;
            int c4 = (e & 15) * 4;
            *(float4*)&sb[(j0 + row) * V + i0 + c4] = *(float4*)&xi_t[row][c4];
        }
    }
}

// ---------------- stage 2 (tf32 tensor): gcn = relu(Y0 + tmp@Z1 + tmp^2@Z2) ----------------
// Z1 = diag(r)Y1, Z2 = diag(r^2)Y2. Grid (4 it, 64 b), 256 thr (8 warps).
// Warp tile: 16 rows x 32 cols. Also normalizes s in place, computes loss.
__global__ __launch_bounds__(256) void tf32_gemm_kernel(
    float* __restrict__ s_out, float* __restrict__ gcn, float* __restrict__ out_loss) {
    __shared__ unsigned sA[64][36];   // cvt_tf32(tmp), rows i0..i0+63, 32-k chunk
    __shared__ unsigned sZ1[32][72];  // cvt_tf32(r*Y1) [k][c]
    __shared__ unsigned sZ2[32][72];  // cvt_tf32(r^2*Y2) [k][c]
    __shared__ float sR[256];

    const int b = blockIdx.y, it = blockIdx.x;
    const int i0 = it * 64;
    const int t = threadIdx.x;
    const int w = t >> 5, l = t & 31;
    const int g = l >> 2, q4 = l & 3;
    const int wr = (w & 3) * 16;    // warp row base in tile
    const int nc0 = (w >> 2) * 32;  // warp col base

    // per-column reciprocal for all 256 k
    {
        int base = b * 4 * V + t;
        float cs = g_pc[base] + g_pc[base + V] + g_pc[base + 2 * V] + g_pc[base + 3 * V];
        float r = 1.0f / cs;
        sR[t] = r;
        if (it == 0) {
            float A = g_pA[base] + g_pA[base + V] + g_pA[base + 2 * V] + g_pA[base + 3 * V];
            float B = g_pB[base] + g_pB[base + V] + g_pB[base + 2 * V] + g_pB[base + 3 * V];
            ((float*)sZ1)[t] = A * r * r + ALPHA_C * B * r;
        }
    }
    if (it == 0) {
        float* red = (float*)sZ1;
        __syncthreads();
        for (int s = 128; s > 0; s >>= 1) {
            if (t < s) red[t] += red[t + s];
            __syncthreads();
        }
        if (t == 0) g_lossP[b] = red[0];
    }
    __syncthreads();

    float* sb = s_out + (size_t)b * V * V;
    const float* y1g = g_Y + 1 * YSZ + b * V * F;
    const float* y2g = g_Y + 2 * YSZ + b * V * F;

    float acc[4][4];
#pragma unroll
    for (int nt = 0; nt < 4; nt++)
#pragma unroll
        for (int u = 0; u < 4; u++) acc[nt][u] = 0.f;

    for (int ch = 0; ch < 8; ch++) {
        int kc0 = ch * 32;
        // stage A (tmp), normalize+writeback s
        for (int e = t; e < 512; e += 256) {
            int i = e >> 3;
            int k4 = (e & 7) * 4;
            float* addr = &sb[(i0 + i) * V + kc0 + k4];
            float4 v = *(const float4*)addr;
            float4 rv = *(const float4*)&sR[kc0 + k4];
            *(float4*)addr = make_float4(v.x * rv.x, v.y * rv.y, v.z * rv.z, v.w * rv.w);
            sA[i][k4 + 0] = cvt_tf32(v.x);
            sA[i][k4 + 1] = cvt_tf32(v.y);
            sA[i][k4 + 2] = cvt_tf32(v.z);
            sA[i][k4 + 3] = cvt_tf32(v.w);
        }
        // stage Z1/Z2
        for (int e = t; e < 512; e += 256) {
            int k = e >> 4;
            int c4 = (e & 15) * 4;
            float r = sR[kc0 + k];
            float r2 = r * r;
            float4 v1 = *(const float4*)&y1g[(kc0 + k) * F + c4];
            float4 v2 = *(const float4*)&y2g[(kc0 + k) * F + c4];
            sZ1[k][c4 + 0] = cvt_tf32(v1.x * r);
            sZ1[k][c4 + 1] = cvt_tf32(v1.y * r);
            sZ1[k][c4 + 2] = cvt_tf32(v1.z * r);
            sZ1[k][c4 + 3] = cvt_tf32(v1.w * r);
            sZ2[k][c4 + 0] = cvt_tf32(v2.x * r2);
            sZ2[k][c4 + 1] = cvt_tf32(v2.y * r2);
            sZ2[k][c4 + 2] = cvt_tf32(v2.z * r2);
            sZ2[k][c4 + 3] = cvt_tf32(v2.w * r2);
        }
        __syncthreads();

#pragma unroll
        for (int k8 = 0; k8 < 4; k8++) {
            int kc = k8 * 8;
            int ra = wr + g;
            unsigned a0 = sA[ra][kc + q4];
            unsigned a1 = sA[ra + 8][kc + q4];
            unsigned a2 = sA[ra][kc + 4 + q4];
            unsigned a3 = sA[ra + 8][kc + 4 + q4];
            float f0 = __uint_as_float(a0), f1 = __uint_as_float(a1);
            float f2 = __uint_as_float(a2), f3 = __uint_as_float(a3);
            unsigned q0 = cvt_tf32(f0 * f0), q1 = cvt_tf32(f1 * f1);
            unsigned q2 = cvt_tf32(f2 * f2), q3 = cvt_tf32(f3 * f3);
#pragma unroll
            for (int nt = 0; nt < 4; nt++) {
                int ncol = nc0 + nt * 8 + g;
                unsigned b0 = sZ1[kc + q4][ncol];
                unsigned b1 = sZ1[kc + 4 + q4][ncol];
                mma_tf32(acc[nt], a0, a1, a2, a3, b0, b1);
                unsigned c0 = sZ2[kc + q4][ncol];
                unsigned c1 = sZ2[kc + 4 + q4][ncol];
                mma_tf32(acc[nt], q0, q1, q2, q3, c0, c1);
            }
        }
        __syncthreads();
    }

    // epilogue: gcn = relu(Y0 + acc)
    const float* y0 = g_Y + b * V * F;
    int r0 = i0 + wr + g, r1 = r0 + 8;
#pragma unroll
    for (int nt = 0; nt < 4; nt++) {
        int col = nc0 + nt * 8 + 2 * q4;
        float2 ya = *(const float2*)&y0[r0 * F + col];
        float2 yb = *(const float2*)&y0[r1 * F + col];
        float2 oa = make_float2(fmaxf(acc[nt][0] + ya.x, 0.f), fmaxf(acc[nt][1] + ya.y, 0.f));
        float2 ob = make_float2(fmaxf(acc[nt][2] + yb.x, 0.f), fmaxf(acc[nt][3] + yb.y, 0.f));
        *(float2*)&gcn[b * V * C + r0 * C + col] = oa;
        *(float2*)&gcn[b * V * C + r1 * C + col] = ob;
    }

    // loss finisher: globally last block writes the scalar
    __threadfence();
    __syncthreads();
    if (t == 0) {
        int og = atomicAdd(&g_cntG, 1);
        if (og == NB * 4 - 1) {
            g_cntG = 0;  // reset for next graph replay
            __threadfence();
            float acc = 0.f;
#pragma unroll 8
            for (int i = 0; i < NB; i++) acc += g_lossP[i];
            *out_loss = acc;
        }
    }
}

// ---------------- launch ----------------
extern "C" void kernel_launch(void* const* d_in, const int* in_sizes, int n_in,
                              void* d_out, int out_size) {
    const float* x = (const float*)d_in[0];      // (64,256,64)
    const float* a = (const float*)d_in[1];      // (64,)
    const float* theta = (const float*)d_in[2];  // (3,64,64)

    float* out = (float*)d_out;
    float* gcn = out;                                 // NB*V*C
    float* s_out = out + (size_t)NB * V * C;          // NB*V*V
    float* loss = out + (size_t)NB * V * C + (size_t)NB * V * V;  // 1

    mega1_kernel<<<N_PW + N_YG, 256>>>(x, a, theta, s_out);

    dim3 gB(4, NB);
    tf32_gemm_kernel<<<gB, 256>>>(s_out, gcn, loss);
}